// round 8
// baseline (speedup 1.0000x reference)
#include <cuda_runtime.h>
#include <math.h>

// ---------------- device scratch ----------------
__device__ float g_blur[4 * 224 * 224 * 256];   // blurred feats, layout [b][y][x][c]
__device__ float g_wp[81 * 256];                // weights repacked [k*9+tap][c]
__device__ int   g_mask_mode;                   // 0=uint8, 1=int32, 2=float32

// packed f32x2 helpers
#define PACK2(d, x, y)  asm("mov.b64 %0, {%1, %2};" : "=l"(d) : "f"(x), "f"(y))
#define UNPACK2(x, y, d) asm("mov.b64 {%0, %1}, %2;" : "=f"(x), "=f"(y) : "l"(d))
#define FMA2(acc, a, b) asm("fma.rn.f32x2 %0, %1, %2, %3;" : "=l"(acc) : "l"(a), "l"(b), "l"(acc))

// ---------------- mask dtype detection ----------------
__global__ void detect_mask_kernel(const unsigned* __restrict__ m) {
    int lane = threadIdx.x;  // 32 threads
    int fcount = 0, zocount = 0;
#pragma unroll
    for (int i = 0; i < 8; i++) {
        unsigned w = m[lane * 8 + i];
        if (w == 0x3f800000u) fcount++;
        if (w <= 1u) zocount++;
    }
#pragma unroll
    for (int o = 16; o; o >>= 1) {
        fcount  += __shfl_xor_sync(0xffffffffu, fcount, o);
        zocount += __shfl_xor_sync(0xffffffffu, zocount, o);
    }
    if (lane == 0) g_mask_mode = (fcount > 0) ? 2 : ((zocount == 256) ? 1 : 0);
}

// ---------------- weight repack: (9,256,3,3) -> [k*9+tap][c] ----------------
__global__ void repack_kernel(const float* __restrict__ ak) {
    int idx = blockIdx.x * 256 + threadIdx.x;  // 81 blocks * 256 = 20736
    int c  = idx & 255;
    int kt = idx >> 8;           // k*9 + tap, 0..80
    int k = kt / 9, tap = kt - k * 9;
    g_wp[idx] = ak[(k * 256 + c) * 9 + tap];
}

// ---------------- separable 5x5 gaussian blur (round-3 proven config) ------
#define BLUR_SMEM (32 * 593 * 4)

__global__ void __launch_bounds__(512, 2) blur_kernel(const float* __restrict__ hr) {
    extern __shared__ float s_v[];

    const float C = -1.4142135623730951f;
    float tb[5]; float s = 0.f;
#pragma unroll
    for (int j = 0; j < 5; j++) { float d = (float)(j - 2); tb[j] = expf(d * d * C); s += tb[j]; }
#pragma unroll
    for (int j = 0; j < 5; j++) tb[j] = tb[j] / s;

    int b = blockIdx.z, cb = blockIdx.y;
    int tx = blockIdx.x % 7, ty = blockIdx.x / 7;
    int x0 = tx * 32, y0 = ty * 16;
    int t = threadIdx.x;

    for (int j = t; j < 1152; j += 512) {
        int ch = j / 36, lx = j - ch * 36;
        int ix = x0 - 2 + lx;
        bool vx = (ix >= 0 && ix < 224);
        const float* base = hr + ((long)(b * 256 + cb * 32 + ch) * 224) * 224 + ix;
        float w0 = 0.f, w1 = 0.f, w2 = 0.f, w3 = 0.f, w4 = 0.f;
        float* ov = s_v + ch * 593 + lx;
#pragma unroll
        for (int yy = 0; yy < 20; yy++) {
            int iy = y0 - 2 + yy;
            float v = (vx && iy >= 0 && iy < 224) ? base[iy * 224] : 0.f;
            w0 = w1; w1 = w2; w2 = w3; w3 = w4; w4 = v;
            if (yy >= 4) {
                float o = w0*tb[0] + w1*tb[1] + w2*tb[2] + w3*tb[3] + w4*tb[4];
                ov[(yy - 4) * 37] = o;
            }
        }
    }
    __syncthreads();

    {
        int ch = t & 31, yr = t >> 5;
        const float* vp = s_v + ch * 593 + yr * 37;
        float* ob = g_blur + ((long)(b * 224 + y0 + yr) * 224 + x0) * 256 + cb * 32 + ch;
        float a0 = vp[0], a1 = vp[1], a2 = vp[2], a3 = vp[3];
#pragma unroll
        for (int x = 0; x < 32; x++) {
            float a4 = vp[x + 4];
            float o = a0*tb[0] + a1*tb[1] + a2*tb[2] + a3*tb[3] + a4*tb[4];
            ob[x * 256] = o;
            a0 = a1; a1 = a2; a2 = a3; a3 = a4;
        }
    }
}

// ---------------- fused logits + softmax + einsum v5 (FFMA2 + k-split) -----
// CTA: 2x8 output tile, 768 threads, 1 CTA/SM (weights L1-resident).
// s_blur: 85 rows x 260 floats (parity-split 5x17 region):
//   even rix: row = riy*9 + rix/2 ; odd rix: row = 45 + riy*8 + rix/2
// phase B thread: cs4 = t&63 (4-ch float4 slice), kg = (t>>6)%3, pg = t/192
//   pg -> py = pg>>1, xh = pg&1; pixels px = 4*xh + i, i = 0..3
//   packed acc2[3][4] (f32x2 over channel pairs); per tap: 3 LDG.128 (w),
//   4 LDS.128 (v), 24 FFMA2.
// warp = fixed (kg,pg), lanes = 32 consecutive c4 (128 ch) -> butterfly,
// then 2-warp combine in smem.
#define FUSED_SMEM ((22100 + 288 + 144 + 144) * 4)

__global__ void __launch_bounds__(768) fused_kernel(
    const void* __restrict__ maskp,
    const float* __restrict__ kbias,
    const float* __restrict__ lbias,
    float* __restrict__ out)
{
    extern __shared__ float sm[];
    float* s_blur  = sm;             // 22100
    float* s_red   = sm + 22100;     // 288 = 24 warps x 12
    float* s_logit = sm + 22388;     // 144
    float* s_attn  = sm + 22532;     // 144

    int t = threadIdx.x;
    int b = blockIdx.z;
    int x0o = blockIdx.x * 8, y0o = blockIdx.y * 2;
    int rx0 = 2 * x0o - 1, ry0 = 2 * y0o - 1;

    // ---- load 5x17 blurred region (85 rows x 256ch), 12 row-streams ----
    {
        int c4 = t & 63, rr = t >> 6;   // rr 0..11
        const float* gb = g_blur + (long)b * 224 * 224 * 256 + c4 * 4;
        for (int row = rr; row < 85; row += 12) {
            int riy, rix;
            if (row < 45) { riy = row / 9;  rix = 2 * (row - riy * 9); }
            else { int q = row - 45; riy = q >> 3; rix = 2 * (q & 7) + 1; }
            int iy = ry0 + riy, ix = rx0 + rix;
            float4 v = make_float4(0.f, 0.f, 0.f, 0.f);
            if (iy >= 0 && iy < 224 && ix >= 0 && ix < 224)
                v = *(const float4*)(gb + ((long)iy * 224 + ix) * 256);
            *(float4*)(s_blur + row * 260 + c4 * 4) = v;
        }
    }
    __syncthreads();

    // ---- phase B: logits, thread tile 4px x 3k x 4ch, packed FFMA2 ----
    {
        int cs4 = t & 63;
        int kg  = (t >> 6) % 3;
        int pg  = t / 192;               // 0..3
        int py = pg >> 1, xh = pg & 1;
        const float4* sb4 = (const float4*)s_blur;   // row stride 65 float4
        const float4* wp4 = (const float4*)g_wp;     // kt stride 64 float4

        unsigned long long acc2[3][4];
#pragma unroll
        for (int k = 0; k < 3; k++)
#pragma unroll
            for (int i = 0; i < 4; i++) acc2[k][i] = 0ull;

#pragma unroll
        for (int dy = 0; dy < 3; dy++) {
            int riy = 2 * py + dy;
            int re = riy * 9 + 4 * xh;        // even-rix base (dx=0)
            int ro = 45 + riy * 8 + 4 * xh;   // odd-rix base
#pragma unroll
            for (int dx = 0; dx < 3; dx++) {
                int rbase = (dx == 1) ? ro : (re + (dx >> 1));
                int tap = dy * 3 + dx;
                // preload 3 weight vectors (this thread's k-group)
                unsigned long long wlo[3], whi[3];
#pragma unroll
                for (int k = 0; k < 3; k++) {
                    float4 w = __ldg(&wp4[((kg * 3 + k) * 9 + tap) * 64 + cs4]);
                    PACK2(wlo[k], w.x, w.y);
                    PACK2(whi[k], w.z, w.w);
                }
#pragma unroll
                for (int i = 0; i < 4; i++) {
                    float4 v = sb4[(rbase + i) * 65 + cs4];
                    unsigned long long vlo, vhi;
                    PACK2(vlo, v.x, v.y);
                    PACK2(vhi, v.z, v.w);
#pragma unroll
                    for (int k = 0; k < 3; k++) {
                        FMA2(acc2[k][i], vlo, wlo[k]);
                        FMA2(acc2[k][i], vhi, whi[k]);
                    }
                }
            }
        }

        // unpack + butterfly over 32 lanes (= 128 channels)
        float acc[3][4];
#pragma unroll
        for (int k = 0; k < 3; k++)
#pragma unroll
            for (int i = 0; i < 4; i++) {
                float lo, hi;
                UNPACK2(lo, hi, acc2[k][i]);
                acc[k][i] = lo + hi;
            }
#pragma unroll
        for (int o = 16; o; o >>= 1)
#pragma unroll
            for (int k = 0; k < 3; k++)
#pragma unroll
                for (int i = 0; i < 4; i++)
                    acc[k][i] += __shfl_xor_sync(0xffffffffu, acc[k][i], o);

        int w = t >> 5, lane = t & 31;
        if (lane == 0) {
#pragma unroll
            for (int k = 0; k < 3; k++)
#pragma unroll
                for (int i = 0; i < 4; i++)
                    s_red[w * 12 + k * 4 + i] = acc[k][i];
        }
    }
    __syncthreads();

    // ---- combine the two c4-half warps -> logits ----
    if (t < 144) {
        int p = t / 9, kk = t - p * 9;
        int i = p & 3;
        int pg = (p >> 3) * 2 + ((p >> 2) & 1);
        int kg = kk / 3, k = kk - kg * 3;
        int w0 = pg * 6 + kg * 2;
        s_logit[p * 9 + kk] = s_red[w0 * 12 + k * 4 + i]
                            + s_red[(w0 + 1) * 12 + k * 4 + i];
    }
    __syncthreads();

    // ---- softmax over 9 with kbias + keep_mask + logit_bias ----
    if (t < 16) {
        int p = t;
        int oy = y0o + (p >> 3), ox = x0o + (p & 7);
        int mm = g_mask_mode;
        float lg[9];
#pragma unroll
        for (int k = 0; k < 9; k++) {
            long midx = ((long)(b * 9 + k) * 112 + oy) * 112 + ox;
            bool keep;
            if (mm == 0)      keep = ((const unsigned char*)maskp)[midx] != 0;
            else if (mm == 1) keep = ((const int*)maskp)[midx] != 0;
            else              keep = ((const float*)maskp)[midx] != 0.f;
            lg[k] = (keep ? (s_logit[p * 9 + k] + kbias[k]) : 0.f) + lbias[k];
        }
        float mx = lg[0];
#pragma unroll
        for (int k = 1; k < 9; k++) mx = fmaxf(mx, lg[k]);
        float e[9]; float ssum = 0.f;
#pragma unroll
        for (int k = 0; k < 9; k++) { e[k] = expf(lg[k] - mx); ssum += e[k]; }
        float invs = 1.0f / ssum;
#pragma unroll
        for (int k = 0; k < 9; k++) s_attn[p * 9 + k] = e[k] * invs;
    }
    __syncthreads();

    // ---- einsum: 512 threads: c = t&255, r = t>>8 ----
    if (t < 512) {
        int c = t & 255, r = t >> 8;
        float ox[8];
#pragma unroll
        for (int x = 0; x < 8; x++) ox[x] = 0.f;
#pragma unroll
        for (int dy = 0; dy < 3; dy++) {
            int riy = 2 * r + dy;
#pragma unroll
            for (int dx = 0; dx < 3; dx++) {
                int k = dy * 3 + dx;
#pragma unroll
                for (int x = 0; x < 8; x++) {
                    int rix = 2 * x + dx;
                    int row = (rix & 1) ? (45 + riy * 8 + (rix >> 1))
                                        : (riy * 9 + (rix >> 1));
                    float v = s_blur[row * 260 + c];
                    float a = s_attn[(r * 8 + x) * 9 + k];
                    ox[x] = fmaf(v, a, ox[x]);
                }
            }
        }
        float* ob = out + ((long)(b * 256 + c) * 112 + y0o + r) * 112 + x0o;
        *(float4*)(ob)     = make_float4(ox[0], ox[1], ox[2], ox[3]);
        *(float4*)(ob + 4) = make_float4(ox[4], ox[5], ox[6], ox[7]);
    }
}

// ---------------- launch ----------------
extern "C" void kernel_launch(void* const* d_in, const int* in_sizes, int n_in,
                              void* d_out, int out_size) {
    const float* hr  = (const float*)d_in[0];
    const float* ak  = (const float*)d_in[1];
    const float* kb  = (const float*)d_in[2];
    const float* lb  = (const float*)d_in[3];
    const void*  msk = d_in[4];
    float* out = (float*)d_out;
    (void)in_sizes; (void)n_in; (void)out_size;

    cudaFuncSetAttribute(blur_kernel,  cudaFuncAttributeMaxDynamicSharedMemorySize, BLUR_SMEM);
    cudaFuncSetAttribute(fused_kernel, cudaFuncAttributeMaxDynamicSharedMemorySize, FUSED_SMEM);

    detect_mask_kernel<<<1, 32>>>((const unsigned*)msk);
    repack_kernel<<<81, 256>>>(ak);
    blur_kernel<<<dim3(98, 8, 4), 512, BLUR_SMEM>>>(hr);
    fused_kernel<<<dim3(14, 56, 4), 768, FUSED_SMEM>>>(msk, kb, lb, out);
}

// round 9
// speedup vs baseline: 1.2230x; 1.2230x over previous
#include <cuda_runtime.h>
#include <cuda_bf16.h>
#include <math.h>

// ---------------- device scratch ----------------
__device__ float g_blur[4 * 224 * 224 * 256];          // blurred feats [b][y][x][c]
__device__ __nv_bfloat16 g_wd[81 * 256];               // delta weights bf16 [k*9+tap][c]
__device__ int   g_mask_mode;                          // 0=uint8, 1=int32, 2=float32

// ---------------- mask dtype detection ----------------
__global__ void detect_mask_kernel(const unsigned* __restrict__ m) {
    int lane = threadIdx.x;  // 32 threads
    int fcount = 0, zocount = 0;
#pragma unroll
    for (int i = 0; i < 8; i++) {
        unsigned w = m[lane * 8 + i];
        if (w == 0x3f800000u) fcount++;
        if (w <= 1u) zocount++;
    }
#pragma unroll
    for (int o = 16; o; o >>= 1) {
        fcount  += __shfl_xor_sync(0xffffffffu, fcount, o);
        zocount += __shfl_xor_sync(0xffffffffu, zocount, o);
    }
    if (lane == 0) g_mask_mode = (fcount > 0) ? 2 : ((zocount == 256) ? 1 : 0);
}

// ---------------- weight repack: (9,256,3,3) -> bf16 delta [k*9+tap][c] ----
__global__ void repack_kernel(const float* __restrict__ ak) {
    int idx = blockIdx.x * 256 + threadIdx.x;  // 81 blocks * 256 = 20736
    int c  = idx & 255;
    int kt = idx >> 8;           // k*9 + tap, 0..80
    int k = kt / 9, tap = kt - k * 9;
    float w = ak[(k * 256 + c) * 9 + tap];
    g_wd[idx] = __float2bfloat16(w - 1.0f);
}

// ---------------- separable 5x5 gaussian blur (proven config) --------------
#define BLUR_SMEM (32 * 593 * 4)

__global__ void __launch_bounds__(512, 2) blur_kernel(const float* __restrict__ hr) {
    extern __shared__ float s_v[];

    const float C = -1.4142135623730951f;
    float tb[5]; float s = 0.f;
#pragma unroll
    for (int j = 0; j < 5; j++) { float d = (float)(j - 2); tb[j] = expf(d * d * C); s += tb[j]; }
#pragma unroll
    for (int j = 0; j < 5; j++) tb[j] = tb[j] / s;

    int b = blockIdx.z, cb = blockIdx.y;
    int tx = blockIdx.x % 7, ty = blockIdx.x / 7;
    int x0 = tx * 32, y0 = ty * 16;
    int t = threadIdx.x;

    for (int j = t; j < 1152; j += 512) {
        int ch = j / 36, lx = j - ch * 36;
        int ix = x0 - 2 + lx;
        bool vx = (ix >= 0 && ix < 224);
        const float* base = hr + ((long)(b * 256 + cb * 32 + ch) * 224) * 224 + ix;
        float w0 = 0.f, w1 = 0.f, w2 = 0.f, w3 = 0.f, w4 = 0.f;
        float* ov = s_v + ch * 593 + lx;
#pragma unroll
        for (int yy = 0; yy < 20; yy++) {
            int iy = y0 - 2 + yy;
            float v = (vx && iy >= 0 && iy < 224) ? base[iy * 224] : 0.f;
            w0 = w1; w1 = w2; w2 = w3; w3 = w4; w4 = v;
            if (yy >= 4) {
                float o = w0*tb[0] + w1*tb[1] + w2*tb[2] + w3*tb[3] + w4*tb[4];
                ov[(yy - 4) * 37] = o;
            }
        }
    }
    __syncthreads();

    {
        int ch = t & 31, yr = t >> 5;
        const float* vp = s_v + ch * 593 + yr * 37;
        float* ob = g_blur + ((long)(b * 224 + y0 + yr) * 224 + x0) * 256 + cb * 32 + ch;
        float a0 = vp[0], a1 = vp[1], a2 = vp[2], a3 = vp[3];
#pragma unroll
        for (int x = 0; x < 32; x++) {
            float a4 = vp[x + 4];
            float o = a0*tb[0] + a1*tb[1] + a2*tb[2] + a3*tb[3] + a4*tb[4];
            ob[x * 256] = o;
            a0 = a1; a1 = a2; a2 = a3; a3 = a4;
        }
    }
}

// ---------------- fused v6: R3 structure + bf16-delta weights + S-term -----
// CTA: 2x8 output tile, 512 threads, 2 CTAs/SM.
// s_blur: 85 rows x 260 floats (parity-split 5x17 region):
//   even rix: row = riy*9 + rix/2 ; odd rix: row = 45 + riy*8 + rix/2
// logit_k = S(pixel) + corr_k,  S = sum_tap T[tap],  T = channel-sum of region
// phase B (correction GEMM): thread = (c4 = t&63, pg = t>>6 [2 px]);
//   per (tap,k): 1 LDG.64 of 4 bf16 deltas + 4 ALU cvt + 8 FFMA.
// smem floats: s_blur 22100 | s_red 288 | s_logit 144 | s_attn 144 | s_T 96
#define FUSED_SMEM ((22100 + 288 + 144 + 144 + 96) * 4)

__global__ void __launch_bounds__(512, 2) fused_kernel(
    const void* __restrict__ maskp,
    const float* __restrict__ kbias,
    const float* __restrict__ lbias,
    float* __restrict__ out)
{
    extern __shared__ float sm[];
    float* s_blur  = sm;             // 22100
    float* s_red   = sm + 22100;     // 288 = 16 warps x 18
    float* s_logit = sm + 22388;     // 144
    float* s_attn  = sm + 22532;     // 144
    float* s_T     = sm + 22676;     // 96 (85 used)

    int t = threadIdx.x;
    int b = blockIdx.z;
    int x0o = blockIdx.x * 8, y0o = blockIdx.y * 2;
    int rx0 = 2 * x0o - 1, ry0 = 2 * y0o - 1;

    // ---- load 5x17 blurred region (85 rows x 256ch), 8 row-streams ----
    {
        int c4 = t & 63, rr = t >> 6;   // 8 row-streams
        const float* gb = g_blur + (long)b * 224 * 224 * 256 + c4 * 4;
        for (int row = rr; row < 85; row += 8) {
            int riy, rix;
            if (row < 45) { riy = row / 9;  rix = 2 * (row - riy * 9); }
            else { int q = row - 45; riy = q >> 3; rix = 2 * (q & 7) + 1; }
            int iy = ry0 + riy, ix = rx0 + rix;
            float4 v = make_float4(0.f, 0.f, 0.f, 0.f);
            if (iy >= 0 && iy < 224 && ix >= 0 && ix < 224)
                v = *(const float4*)(gb + ((long)iy * 224 + ix) * 256);
            *(float4*)(s_blur + row * 260 + c4 * 4) = v;
        }
    }
    __syncthreads();

    // ---- T[pos]: channel sums (warp per position, strided) ----
    {
        int w = t >> 5, lane = t & 31;
        for (int pos = w; pos < 85; pos += 16) {
            const float4* rp = (const float4*)(s_blur + pos * 260);
            float4 a = rp[lane * 2], bq = rp[lane * 2 + 1];   // 8 channels
            float sv = a.x + a.y + a.z + a.w + bq.x + bq.y + bq.z + bq.w;
#pragma unroll
            for (int o = 16; o; o >>= 1) sv += __shfl_xor_sync(0xffffffffu, sv, o);
            if (lane == 0) s_T[pos] = sv;
        }
    }

    // ---- phase B: correction GEMM. thread = (c4, pg), 2 pixels x 9 k ----
    {
        int c4 = t & 63, pg = t >> 6;
        int py = pg >> 2, pql = pg & 3;        // px_i = 2*pql + i
        const float4* sb4 = (const float4*)s_blur;   // row stride 65 float4
        const uint2* wd2 = (const uint2*)g_wd;       // [kt*64 + c4] = 4 bf16

        float acc[9][2];
#pragma unroll
        for (int k = 0; k < 9; k++) { acc[k][0] = 0.f; acc[k][1] = 0.f; }

#pragma unroll
        for (int dy = 0; dy < 3; dy++) {
            int riy = 2 * py + dy;
#pragma unroll
            for (int dx = 0; dx < 3; dx++) {
                int r0, r1;   // rows for pixel i=0,1 : rix = 4*pql + 2*i + dx
                if (dx & 1) { int base = 45 + riy * 8 + 2 * pql; r0 = base; r1 = base + 1; }
                else        { int base = riy * 9 + 2 * pql + (dx >> 1); r0 = base; r1 = base + 1; }
                float4 v0 = sb4[r0 * 65 + c4];
                float4 v1 = sb4[r1 * 65 + c4];
                int tap = dy * 3 + dx;
#pragma unroll
                for (int k = 0; k < 9; k++) {
                    uint2 d = __ldg(&wd2[(k * 9 + tap) * 64 + c4]);
                    float wx = __uint_as_float(d.x << 16);
                    float wy = __uint_as_float(d.x & 0xFFFF0000u);
                    float wz = __uint_as_float(d.y << 16);
                    float ww = __uint_as_float(d.y & 0xFFFF0000u);
                    acc[k][0] = fmaf(v0.x, wx, acc[k][0]);
                    acc[k][0] = fmaf(v0.y, wy, acc[k][0]);
                    acc[k][0] = fmaf(v0.z, wz, acc[k][0]);
                    acc[k][0] = fmaf(v0.w, ww, acc[k][0]);
                    acc[k][1] = fmaf(v1.x, wx, acc[k][1]);
                    acc[k][1] = fmaf(v1.y, wy, acc[k][1]);
                    acc[k][1] = fmaf(v1.z, wz, acc[k][1]);
                    acc[k][1] = fmaf(v1.w, ww, acc[k][1]);
                }
            }
        }

        // warp butterfly over the 32 c4-lanes (128 channels)
#pragma unroll
        for (int o = 16; o; o >>= 1)
#pragma unroll
            for (int k = 0; k < 9; k++) {
                acc[k][0] += __shfl_xor_sync(0xffffffffu, acc[k][0], o);
                acc[k][1] += __shfl_xor_sync(0xffffffffu, acc[k][1], o);
            }
        int w = t >> 5, lane = t & 31;
        if (lane == 0) {
#pragma unroll
            for (int k = 0; k < 9; k++) {
                s_red[w * 18 + k * 2 + 0] = acc[k][0];
                s_red[w * 18 + k * 2 + 1] = acc[k][1];
            }
        }
    }
    __syncthreads();

    // ---- combine halves -> correction logits ----
    if (t < 144) {
        int p = t / 9, k = t - p * 9;
        int pg = p >> 1, i = p & 1;
        s_logit[p * 9 + k] = s_red[(2 * pg) * 18 + k * 2 + i]
                           + s_red[(2 * pg + 1) * 18 + k * 2 + i];
    }
    __syncthreads();

    // ---- softmax over 9: logit = S + corr + kbias, masked, + lbias ----
    if (t < 16) {
        int p = t;
        int py = p >> 3, px = p & 7;
        int oy = y0o + py, ox = x0o + px;
        // S = sum of 9 T taps
        float S = 0.f;
#pragma unroll
        for (int dy = 0; dy < 3; dy++) {
            int riy = 2 * py + dy;
#pragma unroll
            for (int dx = 0; dx < 3; dx++) {
                int rix = 2 * px + dx;
                int row = (rix & 1) ? (45 + riy * 8 + (rix >> 1))
                                    : (riy * 9 + (rix >> 1));
                S += s_T[row];
            }
        }
        int mm = g_mask_mode;
        float lg[9];
#pragma unroll
        for (int k = 0; k < 9; k++) {
            long midx = ((long)(b * 9 + k) * 112 + oy) * 112 + ox;
            bool keep;
            if (mm == 0)      keep = ((const unsigned char*)maskp)[midx] != 0;
            else if (mm == 1) keep = ((const int*)maskp)[midx] != 0;
            else              keep = ((const float*)maskp)[midx] != 0.f;
            lg[k] = (keep ? (S + s_logit[p * 9 + k] + kbias[k]) : 0.f) + lbias[k];
        }
        float mx = lg[0];
#pragma unroll
        for (int k = 1; k < 9; k++) mx = fmaxf(mx, lg[k]);
        float e[9]; float ssum = 0.f;
#pragma unroll
        for (int k = 0; k < 9; k++) { e[k] = expf(lg[k] - mx); ssum += e[k]; }
        float invs = 1.0f / ssum;
#pragma unroll
        for (int k = 0; k < 9; k++) s_attn[p * 9 + k] = e[k] * invs;
    }
    __syncthreads();

    // ---- einsum: thread = (c in 0..255, r = t>>8), 8 x-outputs each ----
    {
        int c = t & 255, r = t >> 8;
        float ox[8];
#pragma unroll
        for (int x = 0; x < 8; x++) ox[x] = 0.f;
#pragma unroll
        for (int dy = 0; dy < 3; dy++) {
            int riy = 2 * r + dy;
#pragma unroll
            for (int dx = 0; dx < 3; dx++) {
                int k = dy * 3 + dx;
#pragma unroll
                for (int x = 0; x < 8; x++) {
                    int rix = 2 * x + dx;
                    int row = (rix & 1) ? (45 + riy * 8 + (rix >> 1))
                                        : (riy * 9 + (rix >> 1));
                    float v = s_blur[row * 260 + c];
                    float a = s_attn[(r * 8 + x) * 9 + k];
                    ox[x] = fmaf(v, a, ox[x]);
                }
            }
        }
        float* ob = out + ((long)(b * 256 + c) * 112 + y0o + r) * 112 + x0o;
        *(float4*)(ob)     = make_float4(ox[0], ox[1], ox[2], ox[3]);
        *(float4*)(ob + 4) = make_float4(ox[4], ox[5], ox[6], ox[7]);
    }
}

// ---------------- launch ----------------
extern "C" void kernel_launch(void* const* d_in, const int* in_sizes, int n_in,
                              void* d_out, int out_size) {
    const float* hr  = (const float*)d_in[0];
    const float* ak  = (const float*)d_in[1];
    const float* kb  = (const float*)d_in[2];
    const float* lb  = (const float*)d_in[3];
    const void*  msk = d_in[4];
    float* out = (float*)d_out;
    (void)in_sizes; (void)n_in; (void)out_size;

    cudaFuncSetAttribute(blur_kernel,  cudaFuncAttributeMaxDynamicSharedMemorySize, BLUR_SMEM);
    cudaFuncSetAttribute(fused_kernel, cudaFuncAttributeMaxDynamicSharedMemorySize, FUSED_SMEM);

    detect_mask_kernel<<<1, 32>>>((const unsigned*)msk);
    repack_kernel<<<81, 256>>>(ak);
    blur_kernel<<<dim3(98, 8, 4), 512, BLUR_SMEM>>>(hr);
    fused_kernel<<<dim3(14, 56, 4), 512, FUSED_SMEM>>>(msk, kb, lb, out);
}

// round 10
// speedup vs baseline: 1.3697x; 1.1200x over previous
#include <cuda_runtime.h>
#include <math.h>

// ---------------- device scratch ----------------
__device__ float g_blur[4 * 224 * 224 * 256];   // blurred feats, layout [b][y][x][c]
__device__ float g_wp[81 * 256];                // weights repacked [k*9+tap][c]
__device__ int   g_mask_mode;                   // 0=uint8, 1=int32, 2=float32

// ---------------- mask dtype detection ----------------
__global__ void detect_mask_kernel(const unsigned* __restrict__ m) {
    int lane = threadIdx.x;  // 32 threads
    int fcount = 0, zocount = 0;
#pragma unroll
    for (int i = 0; i < 8; i++) {
        unsigned w = m[lane * 8 + i];
        if (w == 0x3f800000u) fcount++;
        if (w <= 1u) zocount++;
    }
#pragma unroll
    for (int o = 16; o; o >>= 1) {
        fcount  += __shfl_xor_sync(0xffffffffu, fcount, o);
        zocount += __shfl_xor_sync(0xffffffffu, zocount, o);
    }
    if (lane == 0) g_mask_mode = (fcount > 0) ? 2 : ((zocount == 256) ? 1 : 0);
}

// ---------------- weight repack: (9,256,3,3) -> [k*9+tap][c] ----------------
__global__ void repack_kernel(const float* __restrict__ ak) {
    int idx = blockIdx.x * 256 + threadIdx.x;  // 81 blocks * 256 = 20736
    int c  = idx & 255;
    int kt = idx >> 8;           // k*9 + tap, 0..80
    int k = kt / 9, tap = kt - k * 9;
    g_wp[idx] = ak[(k * 256 + c) * 9 + tap];
}

// ---------------- separable 5x5 gaussian blur (proven R3 config) -----------
#define BLUR_SMEM (32 * 593 * 4)

__global__ void __launch_bounds__(512, 2) blur_kernel(const float* __restrict__ hr) {
    extern __shared__ float s_v[];

    const float C = -1.4142135623730951f;
    float tb[5]; float s = 0.f;
#pragma unroll
    for (int j = 0; j < 5; j++) { float d = (float)(j - 2); tb[j] = expf(d * d * C); s += tb[j]; }
#pragma unroll
    for (int j = 0; j < 5; j++) tb[j] = tb[j] / s;

    int b = blockIdx.z, cb = blockIdx.y;
    int tx = blockIdx.x % 7, ty = blockIdx.x / 7;
    int x0 = tx * 32, y0 = ty * 16;
    int t = threadIdx.x;

    for (int j = t; j < 1152; j += 512) {
        int ch = j / 36, lx = j - ch * 36;
        int ix = x0 - 2 + lx;
        bool vx = (ix >= 0 && ix < 224);
        const float* base = hr + ((long)(b * 256 + cb * 32 + ch) * 224) * 224 + ix;
        float w0 = 0.f, w1 = 0.f, w2 = 0.f, w3 = 0.f, w4 = 0.f;
        float* ov = s_v + ch * 593 + lx;
#pragma unroll
        for (int yy = 0; yy < 20; yy++) {
            int iy = y0 - 2 + yy;
            float v = (vx && iy >= 0 && iy < 224) ? base[iy * 224] : 0.f;
            w0 = w1; w1 = w2; w2 = w3; w3 = w4; w4 = v;
            if (yy >= 4) {
                float o = w0*tb[0] + w1*tb[1] + w2*tb[2] + w3*tb[3] + w4*tb[4];
                ov[(yy - 4) * 37] = o;
            }
        }
    }
    __syncthreads();

    {
        int ch = t & 31, yr = t >> 5;
        const float* vp = s_v + ch * 593 + yr * 37;
        float* ob = g_blur + ((long)(b * 224 + y0 + yr) * 224 + x0) * 256 + cb * 32 + ch;
        float a0 = vp[0], a1 = vp[1], a2 = vp[2], a3 = vp[3];
#pragma unroll
        for (int x = 0; x < 32; x++) {
            float a4 = vp[x + 4];
            float o = a0*tb[0] + a1*tb[1] + a2*tb[2] + a3*tb[3] + a4*tb[4];
            ob[x * 256] = o;
            a0 = a1; a1 = a2; a2 = a3; a3 = a4;
        }
    }
}

// ---------------- fused v7: k-split phase B + float4 einsum ----------------
// CTA: 2x8 output tile, 512 threads, 2 CTAs/SM, fp32 weights via __ldg.
// s_blur: 85 rows x 260 floats (parity-split 5x17 region):
//   even rix: row = riy*9 + rix/2 ; odd rix: row = 45 + riy*8 + rix/2
// phase B thread: c4 = t&63, sub = t>>6: kg = sub>>2 (k 0-3 / 4-8),
//   pg = sub&3 -> py = pg>>1, xh = pg&1, pixels px = 4*xh + i (i=0..3)
//   per tap: KN w-LDG.128 + 4 v-LDS.128 + 16*KN FMA; acc[KN][4].
// smem floats: s_blur 22100 | s_red 320 | s_logit 144 | s_attn 144
#define FUSED_SMEM ((22100 + 320 + 144 + 144) * 4)

template<int K0, int KN>
__device__ __forceinline__ void phaseB_body(
    const float4* __restrict__ sb4, const float4* __restrict__ wp4,
    float* __restrict__ s_red, int c4, int py, int xh, int w_idx, int lane)
{
    float acc[KN][4];
#pragma unroll
    for (int k = 0; k < KN; k++)
#pragma unroll
        for (int i = 0; i < 4; i++) acc[k][i] = 0.f;

#pragma unroll
    for (int dy = 0; dy < 3; dy++) {
        int riy = 2 * py + dy;
        int re = riy * 9 + 4 * xh;        // even-rix base (dx=0)
        int ro = 45 + riy * 8 + 4 * xh;   // odd-rix base
#pragma unroll
        for (int dx = 0; dx < 3; dx++) {
            int rbase = (dx == 1) ? ro : (re + (dx >> 1));
            int tap = dy * 3 + dx;
            float4 w[KN];
#pragma unroll
            for (int k = 0; k < KN; k++)
                w[k] = __ldg(&wp4[((K0 + k) * 9 + tap) * 64 + c4]);
#pragma unroll
            for (int i = 0; i < 4; i++) {
                float4 v = sb4[(rbase + i) * 65 + c4];
#pragma unroll
                for (int k = 0; k < KN; k++) {
                    float a = acc[k][i];
                    a = fmaf(v.x, w[k].x, a);
                    a = fmaf(v.y, w[k].y, a);
                    a = fmaf(v.z, w[k].z, a);
                    a = fmaf(v.w, w[k].w, a);
                    acc[k][i] = a;
                }
            }
        }
    }

    // butterfly over 32 lanes (128 channels); write warp partials
#pragma unroll
    for (int o = 16; o; o >>= 1)
#pragma unroll
        for (int k = 0; k < KN; k++)
#pragma unroll
            for (int i = 0; i < 4; i++)
                acc[k][i] += __shfl_xor_sync(0xffffffffu, acc[k][i], o);
    if (lane == 0) {
#pragma unroll
        for (int k = 0; k < KN; k++)
#pragma unroll
            for (int i = 0; i < 4; i++)
                s_red[w_idx * 20 + k * 4 + i] = acc[k][i];
    }
}

__global__ void __launch_bounds__(512, 2) fused_kernel(
    const void* __restrict__ maskp,
    const float* __restrict__ kbias,
    const float* __restrict__ lbias,
    float* __restrict__ out)
{
    extern __shared__ float sm[];
    float* s_blur  = sm;             // 22100
    float* s_red   = sm + 22100;     // 320 = 16 warps x 20
    float* s_logit = sm + 22420;     // 144
    float* s_attn  = sm + 22564;     // 144

    int t = threadIdx.x;
    int b = blockIdx.z;
    int x0o = blockIdx.x * 8, y0o = blockIdx.y * 2;
    int rx0 = 2 * x0o - 1, ry0 = 2 * y0o - 1;

    // ---- load 5x17 blurred region (85 rows x 256ch), 8 row-streams ----
    {
        int c4 = t & 63, rr = t >> 6;
        const float* gb = g_blur + (long)b * 224 * 224 * 256 + c4 * 4;
        for (int row = rr; row < 85; row += 8) {
            int riy, rix;
            if (row < 45) { riy = row / 9;  rix = 2 * (row - riy * 9); }
            else { int q = row - 45; riy = q >> 3; rix = 2 * (q & 7) + 1; }
            int iy = ry0 + riy, ix = rx0 + rix;
            float4 v = make_float4(0.f, 0.f, 0.f, 0.f);
            if (iy >= 0 && iy < 224 && ix >= 0 && ix < 224)
                v = *(const float4*)(gb + ((long)iy * 224 + ix) * 256);
            *(float4*)(s_blur + row * 260 + c4 * 4) = v;
        }
    }
    __syncthreads();

    // ---- phase B: logits, k-split 4/5, 4 px per thread ----
    {
        int c4 = t & 63;
        int sub = t >> 6;           // 0..7
        int kg = sub >> 2;          // 0..1
        int pg = sub & 3;           // py = pg>>1, xh = pg&1
        int py = pg >> 1, xh = pg & 1;
        int w_idx = t >> 5, lane = t & 31;
        const float4* sb4 = (const float4*)s_blur;   // row stride 65 float4
        const float4* wp4 = (const float4*)g_wp;     // kt stride 64 float4

        if (kg == 0) phaseB_body<0, 4>(sb4, wp4, s_red, c4, py, xh, w_idx, lane);
        else         phaseB_body<4, 5>(sb4, wp4, s_red, c4, py, xh, w_idx, lane);
    }
    __syncthreads();

    // ---- combine 2 warp-halves + kbias -> logits ----
    if (t < 144) {
        int p = t / 9, k = t - p * 9;
        int py = p >> 3, px = p & 7;
        int xh = px >> 2, i = px & 3;
        int pg = py * 2 + xh;
        int kg = (k >= 4) ? 1 : 0;
        int kl = k - (kg ? 4 : 0);
        int w0 = (kg * 4 + pg) * 2;
        s_logit[p * 9 + k] = kbias[k]
                           + s_red[w0 * 20 + kl * 4 + i]
                           + s_red[(w0 + 1) * 20 + kl * 4 + i];
    }
    __syncthreads();

    // ---- softmax over 9 with keep_mask + logit_bias ----
    if (t < 16) {
        int p = t;
        int oy = y0o + (p >> 3), ox = x0o + (p & 7);
        int mm = g_mask_mode;
        float lg[9];
#pragma unroll
        for (int k = 0; k < 9; k++) {
            long midx = ((long)(b * 9 + k) * 112 + oy) * 112 + ox;
            bool keep;
            if (mm == 0)      keep = ((const unsigned char*)maskp)[midx] != 0;
            else if (mm == 1) keep = ((const int*)maskp)[midx] != 0;
            else              keep = ((const float*)maskp)[midx] != 0.f;
            lg[k] = (keep ? s_logit[p * 9 + k] : 0.f) + lbias[k];
        }
        float mx = lg[0];
#pragma unroll
        for (int k = 1; k < 9; k++) mx = fmaxf(mx, lg[k]);
        float e[9]; float ssum = 0.f;
#pragma unroll
        for (int k = 0; k < 9; k++) { e[k] = expf(lg[k] - mx); ssum += e[k]; }
        float invs = 1.0f / ssum;
#pragma unroll
        for (int k = 0; k < 9; k++) s_attn[p * 9 + k] = e[k] * invs;
    }
    __syncthreads();

    // ---- einsum v2: thread = (px = t&7, c4 = t>>3), float4 channels ----
    {
        int px = t & 7, c4 = t >> 3;   // c4 0..63
        const float4* sb4 = (const float4*)s_blur;
#pragma unroll
        for (int r = 0; r < 2; r++) {
            float4 o = make_float4(0.f, 0.f, 0.f, 0.f);
#pragma unroll
            for (int dy = 0; dy < 3; dy++) {
                int riy = 2 * r + dy;
#pragma unroll
                for (int dx = 0; dx < 3; dx++) {
                    int rix = 2 * px + dx;
                    int row = (rix & 1) ? (45 + riy * 8 + (rix >> 1))
                                        : (riy * 9 + (rix >> 1));
                    float4 v = sb4[row * 65 + c4];
                    float a = s_attn[(r * 8 + px) * 9 + dy * 3 + dx];
                    o.x = fmaf(v.x, a, o.x);
                    o.y = fmaf(v.y, a, o.y);
                    o.z = fmaf(v.z, a, o.z);
                    o.w = fmaf(v.w, a, o.w);
                }
            }
            long base = ((long)(b * 256 + c4 * 4) * 112 + y0o + r) * 112 + x0o + px;
            const long cs = (long)112 * 112;
            out[base]          = o.x;
            out[base + cs]     = o.y;
            out[base + 2 * cs] = o.z;
            out[base + 3 * cs] = o.w;
        }
    }
}

// ---------------- launch ----------------
extern "C" void kernel_launch(void* const* d_in, const int* in_sizes, int n_in,
                              void* d_out, int out_size) {
    const float* hr  = (const float*)d_in[0];
    const float* ak  = (const float*)d_in[1];
    const float* kb  = (const float*)d_in[2];
    const float* lb  = (const float*)d_in[3];
    const void*  msk = d_in[4];
    float* out = (float*)d_out;
    (void)in_sizes; (void)n_in; (void)out_size;

    cudaFuncSetAttribute(blur_kernel,  cudaFuncAttributeMaxDynamicSharedMemorySize, BLUR_SMEM);
    cudaFuncSetAttribute(fused_kernel, cudaFuncAttributeMaxDynamicSharedMemorySize, FUSED_SMEM);

    detect_mask_kernel<<<1, 32>>>((const unsigned*)msk);
    repack_kernel<<<81, 256>>>(ak);
    blur_kernel<<<dim3(98, 8, 4), 512, BLUR_SMEM>>>(hr);
    fused_kernel<<<dim3(14, 56, 4), 512, FUSED_SMEM>>>(msk, kb, lb, out);
}

// round 11
// speedup vs baseline: 1.4023x; 1.0238x over previous
#include <cuda_runtime.h>
#include <math.h>

// ---------------- device scratch ----------------
__device__ float g_blur[4 * 224 * 224 * 256];   // blurred feats, layout [b][y][x][c]
__device__ float g_wp[81 * 256];                // weights repacked [k*9+tap][c]
__device__ int   g_mask_mode;                   // 0=uint8, 1=int32, 2=float32

// ---------------- mask dtype detection ----------------
__global__ void detect_mask_kernel(const unsigned* __restrict__ m) {
    int lane = threadIdx.x;  // 32 threads
    int fcount = 0, zocount = 0;
#pragma unroll
    for (int i = 0; i < 8; i++) {
        unsigned w = m[lane * 8 + i];
        if (w == 0x3f800000u) fcount++;
        if (w <= 1u) zocount++;
    }
#pragma unroll
    for (int o = 16; o; o >>= 1) {
        fcount  += __shfl_xor_sync(0xffffffffu, fcount, o);
        zocount += __shfl_xor_sync(0xffffffffu, zocount, o);
    }
    if (lane == 0) g_mask_mode = (fcount > 0) ? 2 : ((zocount == 256) ? 1 : 0);
}

// ---------------- weight repack: (9,256,3,3) -> [k*9+tap][c] ----------------
__global__ void repack_kernel(const float* __restrict__ ak) {
    int idx = blockIdx.x * 256 + threadIdx.x;  // 81 blocks * 256 = 20736
    int c  = idx & 255;
    int kt = idx >> 8;           // k*9 + tap, 0..80
    int k = kt / 9, tap = kt - k * 9;
    g_wp[idx] = ak[(k * 256 + c) * 9 + tap];
}

// ---------------- separable 5x5 gaussian blur (proven R3 config) -----------
#define BLUR_SMEM (32 * 593 * 4)

__global__ void __launch_bounds__(512, 2) blur_kernel(const float* __restrict__ hr) {
    extern __shared__ float s_v[];

    const float C = -1.4142135623730951f;
    float tb[5]; float s = 0.f;
#pragma unroll
    for (int j = 0; j < 5; j++) { float d = (float)(j - 2); tb[j] = expf(d * d * C); s += tb[j]; }
#pragma unroll
    for (int j = 0; j < 5; j++) tb[j] = tb[j] / s;

    int b = blockIdx.z, cb = blockIdx.y;
    int tx = blockIdx.x % 7, ty = blockIdx.x / 7;
    int x0 = tx * 32, y0 = ty * 16;
    int t = threadIdx.x;

    for (int j = t; j < 1152; j += 512) {
        int ch = j / 36, lx = j - ch * 36;
        int ix = x0 - 2 + lx;
        bool vx = (ix >= 0 && ix < 224);
        const float* base = hr + ((long)(b * 256 + cb * 32 + ch) * 224) * 224 + ix;
        float w0 = 0.f, w1 = 0.f, w2 = 0.f, w3 = 0.f, w4 = 0.f;
        float* ov = s_v + ch * 593 + lx;
#pragma unroll
        for (int yy = 0; yy < 20; yy++) {
            int iy = y0 - 2 + yy;
            float v = (vx && iy >= 0 && iy < 224) ? base[iy * 224] : 0.f;
            w0 = w1; w1 = w2; w2 = w3; w3 = w4; w4 = v;
            if (yy >= 4) {
                float o = w0*tb[0] + w1*tb[1] + w2*tb[2] + w3*tb[3] + w4*tb[4];
                ov[(yy - 4) * 37] = o;
            }
        }
    }
    __syncthreads();

    {
        int ch = t & 31, yr = t >> 5;
        const float* vp = s_v + ch * 593 + yr * 37;
        float* ob = g_blur + ((long)(b * 224 + y0 + yr) * 224 + x0) * 256 + cb * 32 + ch;
        float a0 = vp[0], a1 = vp[1], a2 = vp[2], a3 = vp[3];
#pragma unroll
        for (int x = 0; x < 32; x++) {
            float a4 = vp[x + 4];
            float o = a0*tb[0] + a1*tb[1] + a2*tb[2] + a3*tb[3] + a4*tb[4];
            ob[x * 256] = o;
            a0 = a1; a1 = a2; a2 = a3; a3 = a4;
        }
    }
}

// ---------------- fused v8: SMEM-staged weights (double buffer) ------------
// CTA: 2x8 output tile, 512 threads, 2 CTAs/SM.
// s_blur: 85 rows x 260 floats (parity-split 5x17 region):
//   even rix: row = riy*9 + rix/2 ; odd rix: row = 45 + riy*8 + rix/2
// s_w: double buffer, 2 x [9 k][256 c] fp32 (9.2 KB per tap buffer).
// phase B: per tap -> stage next tap's weights (coalesced LDG->STS by all
//   512 threads), compute current tap from SMEM (9 w-LDS.128 + 2 v-LDS.128
//   + 72 FMA per thread), barrier. Weight LDG latency hidden behind compute.
// thread: c4 = t&63, pg = t>>6 -> py = pg>>2, pql = pg&3, px_i = 2*pql + i
// smem floats: s_blur 22100 | s_w 4608 | s_red 288 | s_logit 144 | s_attn 144
#define FUSED_SMEM ((22100 + 4608 + 288 + 144 + 144) * 4)

__device__ __forceinline__ void stage_tap(const float4* __restrict__ wp4,
                                          float* __restrict__ s_w,
                                          int buf, int tap, int t)
{
    // 576 float4 per tap (9 k x 64 c4)
    {
        int k = t >> 6, c4 = t & 63;
        *(float4*)(s_w + ((buf * 9 + k) * 64 + c4) * 4) =
            __ldg(&wp4[(k * 9 + tap) * 64 + c4]);
    }
    if (t < 64) {
        *(float4*)(s_w + ((buf * 9 + 8) * 64 + t) * 4) =
            __ldg(&wp4[(8 * 9 + tap) * 64 + t]);
    }
}

__global__ void __launch_bounds__(512, 2) fused_kernel(
    const void* __restrict__ maskp,
    const float* __restrict__ kbias,
    const float* __restrict__ lbias,
    float* __restrict__ out)
{
    extern __shared__ float sm[];
    float* s_blur  = sm;             // 22100
    float* s_w     = sm + 22100;     // 4608
    float* s_red   = sm + 26708;     // 288 = 16 warps x 18
    float* s_logit = sm + 26996;     // 144
    float* s_attn  = sm + 27140;     // 144

    int t = threadIdx.x;
    int b = blockIdx.z;
    int x0o = blockIdx.x * 8, y0o = blockIdx.y * 2;
    int rx0 = 2 * x0o - 1, ry0 = 2 * y0o - 1;

    const float4* wp4 = (const float4*)g_wp;   // kt stride 64 float4

    // ---- stage tap 0 weights + load 5x17 blurred region concurrently ----
    stage_tap(wp4, s_w, 0, 0, t);
    {
        int c4 = t & 63, rr = t >> 6;
        const float* gb = g_blur + (long)b * 224 * 224 * 256 + c4 * 4;
        for (int row = rr; row < 85; row += 8) {
            int riy, rix;
            if (row < 45) { riy = row / 9;  rix = 2 * (row - riy * 9); }
            else { int q = row - 45; riy = q >> 3; rix = 2 * (q & 7) + 1; }
            int iy = ry0 + riy, ix = rx0 + rix;
            float4 v = make_float4(0.f, 0.f, 0.f, 0.f);
            if (iy >= 0 && iy < 224 && ix >= 0 && ix < 224)
                v = __ldcs((const float4*)(gb + ((long)iy * 224 + ix) * 256));
            *(float4*)(s_blur + row * 260 + c4 * 4) = v;
        }
    }
    __syncthreads();

    // ---- phase B: logits. thread = (c4, pg), 2 pixels x 9 k ----
    {
        int c4 = t & 63, pg = t >> 6;
        int py = pg >> 2, pql = pg & 3;        // px_i = 2*pql + i
        const float4* sb4 = (const float4*)s_blur;   // row stride 65 float4
        const float4* sw4 = (const float4*)s_w;      // [buf*9+k]*64 + c4

        float acc[9][2];
#pragma unroll
        for (int k = 0; k < 9; k++) { acc[k][0] = 0.f; acc[k][1] = 0.f; }

#pragma unroll
        for (int tap = 0; tap < 9; tap++) {
            // stage next tap into the other buffer (overlaps compute)
            if (tap < 8) stage_tap(wp4, s_w, (tap + 1) & 1, tap + 1, t);

            const int dy = tap / 3, dx = tap % 3;   // compile-time (unrolled)
            int riy = 2 * py + dy;
            int r0, r1;   // rows for pixel i=0,1 : rix = 4*pql + 2*i + dx
            if (dx & 1) { int base = 45 + riy * 8 + 2 * pql; r0 = base; r1 = base + 1; }
            else        { int base = riy * 9 + 2 * pql + (dx >> 1); r0 = base; r1 = base + 1; }
            float4 v0 = sb4[r0 * 65 + c4];
            float4 v1 = sb4[r1 * 65 + c4];
            int bufb = (tap & 1) * 9;
#pragma unroll
            for (int k = 0; k < 9; k++) {
                float4 w = sw4[(bufb + k) * 64 + c4];
                acc[k][0] = fmaf(v0.x, w.x, acc[k][0]);
                acc[k][0] = fmaf(v0.y, w.y, acc[k][0]);
                acc[k][0] = fmaf(v0.z, w.z, acc[k][0]);
                acc[k][0] = fmaf(v0.w, w.w, acc[k][0]);
                acc[k][1] = fmaf(v1.x, w.x, acc[k][1]);
                acc[k][1] = fmaf(v1.y, w.y, acc[k][1]);
                acc[k][1] = fmaf(v1.z, w.z, acc[k][1]);
                acc[k][1] = fmaf(v1.w, w.w, acc[k][1]);
            }
            __syncthreads();   // staging of tap+1 visible; buffer rotation safe
        }

        // warp butterfly over the 32 c4-lanes (128 channels)
#pragma unroll
        for (int o = 16; o; o >>= 1)
#pragma unroll
            for (int k = 0; k < 9; k++) {
                acc[k][0] += __shfl_xor_sync(0xffffffffu, acc[k][0], o);
                acc[k][1] += __shfl_xor_sync(0xffffffffu, acc[k][1], o);
            }
        int w = t >> 5, lane = t & 31;
        if (lane == 0) {
#pragma unroll
            for (int k = 0; k < 9; k++) {
                s_red[w * 18 + k * 2 + 0] = acc[k][0];
                s_red[w * 18 + k * 2 + 1] = acc[k][1];
            }
        }
    }
    __syncthreads();

    // ---- combine halves + kbias -> logits ----
    if (t < 144) {
        int p = t / 9, k = t - p * 9;
        int pg = p >> 1, i = p & 1;
        float v = kbias[k] + s_red[(2 * pg) * 18 + k * 2 + i]
                           + s_red[(2 * pg + 1) * 18 + k * 2 + i];
        s_logit[p * 9 + k] = v;
    }
    __syncthreads();

    // ---- softmax over 9 with keep_mask + logit_bias ----
    if (t < 16) {
        int p = t;
        int oy = y0o + (p >> 3), ox = x0o + (p & 7);
        int mm = g_mask_mode;
        float lg[9];
#pragma unroll
        for (int k = 0; k < 9; k++) {
            long midx = ((long)(b * 9 + k) * 112 + oy) * 112 + ox;
            bool keep;
            if (mm == 0)      keep = ((const unsigned char*)maskp)[midx] != 0;
            else if (mm == 1) keep = ((const int*)maskp)[midx] != 0;
            else              keep = ((const float*)maskp)[midx] != 0.f;
            lg[k] = (keep ? s_logit[p * 9 + k] : 0.f) + lbias[k];
        }
        float mx = lg[0];
#pragma unroll
        for (int k = 1; k < 9; k++) mx = fmaxf(mx, lg[k]);
        float e[9]; float ssum = 0.f;
#pragma unroll
        for (int k = 0; k < 9; k++) { e[k] = expf(lg[k] - mx); ssum += e[k]; }
        float invs = 1.0f / ssum;
#pragma unroll
        for (int k = 0; k < 9; k++) s_attn[p * 9 + k] = e[k] * invs;
    }
    __syncthreads();

    // ---- einsum: thread = (px = t&7, c4 = t>>3), float4 channels ----
    {
        int px = t & 7, c4 = t >> 3;   // c4 0..63
        const float4* sb4 = (const float4*)s_blur;
#pragma unroll
        for (int r = 0; r < 2; r++) {
            float4 o = make_float4(0.f, 0.f, 0.f, 0.f);
#pragma unroll
            for (int dy = 0; dy < 3; dy++) {
                int riy = 2 * r + dy;
#pragma unroll
                for (int dx = 0; dx < 3; dx++) {
                    int rix = 2 * px + dx;
                    int row = (rix & 1) ? (45 + riy * 8 + (rix >> 1))
                                        : (riy * 9 + (rix >> 1));
                    float4 v = sb4[row * 65 + c4];
                    float a = s_attn[(r * 8 + px) * 9 + dy * 3 + dx];
                    o.x = fmaf(v.x, a, o.x);
                    o.y = fmaf(v.y, a, o.y);
                    o.z = fmaf(v.z, a, o.z);
                    o.w = fmaf(v.w, a, o.w);
                }
            }
            long base = ((long)(b * 256 + c4 * 4) * 112 + y0o + r) * 112 + x0o + px;
            const long cs = (long)112 * 112;
            out[base]          = o.x;
            out[base + cs]     = o.y;
            out[base + 2 * cs] = o.z;
            out[base + 3 * cs] = o.w;
        }
    }
}

// ---------------- launch ----------------
extern "C" void kernel_launch(void* const* d_in, const int* in_sizes, int n_in,
                              void* d_out, int out_size) {
    const float* hr  = (const float*)d_in[0];
    const float* ak  = (const float*)d_in[1];
    const float* kb  = (const float*)d_in[2];
    const float* lb  = (const float*)d_in[3];
    const void*  msk = d_in[4];
    float* out = (float*)d_out;
    (void)in_sizes; (void)n_in; (void)out_size;

    cudaFuncSetAttribute(blur_kernel,  cudaFuncAttributeMaxDynamicSharedMemorySize, BLUR_SMEM);
    cudaFuncSetAttribute(fused_kernel, cudaFuncAttributeMaxDynamicSharedMemorySize, FUSED_SMEM);

    detect_mask_kernel<<<1, 32>>>((const unsigned*)msk);
    repack_kernel<<<81, 256>>>(ak);
    blur_kernel<<<dim3(98, 8, 4), 512, BLUR_SMEM>>>(hr);
    fused_kernel<<<dim3(14, 56, 4), 512, FUSED_SMEM>>>(msk, kb, lb, out);
}

// round 12
// speedup vs baseline: 1.4114x; 1.0064x over previous
#include <cuda_runtime.h>
#include <math.h>

// ---------------- device scratch ----------------
__device__ float g_blur[4 * 224 * 224 * 256];   // blurred feats, layout [b][y][x][c]
__device__ float g_wp[81 * 256];                // weights repacked [k*9+tap][c]
__device__ int   g_mask_mode;                   // 0=uint8, 1=int32, 2=float32

// ---------------- mask dtype detection ----------------
__global__ void detect_mask_kernel(const unsigned* __restrict__ m) {
    int lane = threadIdx.x;  // 32 threads
    int fcount = 0, zocount = 0;
#pragma unroll
    for (int i = 0; i < 8; i++) {
        unsigned w = m[lane * 8 + i];
        if (w == 0x3f800000u) fcount++;
        if (w <= 1u) zocount++;
    }
#pragma unroll
    for (int o = 16; o; o >>= 1) {
        fcount  += __shfl_xor_sync(0xffffffffu, fcount, o);
        zocount += __shfl_xor_sync(0xffffffffu, zocount, o);
    }
    if (lane == 0) g_mask_mode = (fcount > 0) ? 2 : ((zocount == 256) ? 1 : 0);
}

// ---------------- weight repack: (9,256,3,3) -> [k*9+tap][c] ----------------
__global__ void repack_kernel(const float* __restrict__ ak) {
    int idx = blockIdx.x * 256 + threadIdx.x;  // 81 blocks * 256 = 20736
    int c  = idx & 255;
    int kt = idx >> 8;           // k*9 + tap, 0..80
    int k = kt / 9, tap = kt - k * 9;
    g_wp[idx] = ak[(k * 256 + c) * 9 + tap];
}

// ---------------- separable 5x5 gaussian blur (proven R3 config) -----------
#define BLUR_SMEM (32 * 593 * 4)

__global__ void __launch_bounds__(512, 2) blur_kernel(const float* __restrict__ hr) {
    extern __shared__ float s_v[];

    const float C = -1.4142135623730951f;
    float tb[5]; float s = 0.f;
#pragma unroll
    for (int j = 0; j < 5; j++) { float d = (float)(j - 2); tb[j] = expf(d * d * C); s += tb[j]; }
#pragma unroll
    for (int j = 0; j < 5; j++) tb[j] = tb[j] / s;

    int b = blockIdx.z, cb = blockIdx.y;
    int tx = blockIdx.x % 7, ty = blockIdx.x / 7;
    int x0 = tx * 32, y0 = ty * 16;
    int t = threadIdx.x;

    for (int j = t; j < 1152; j += 512) {
        int ch = j / 36, lx = j - ch * 36;
        int ix = x0 - 2 + lx;
        bool vx = (ix >= 0 && ix < 224);
        const float* base = hr + ((long)(b * 256 + cb * 32 + ch) * 224) * 224 + ix;
        float w0 = 0.f, w1 = 0.f, w2 = 0.f, w3 = 0.f, w4 = 0.f;
        float* ov = s_v + ch * 593 + lx;
#pragma unroll
        for (int yy = 0; yy < 20; yy++) {
            int iy = y0 - 2 + yy;
            float v = (vx && iy >= 0 && iy < 224) ? base[iy * 224] : 0.f;
            w0 = w1; w1 = w2; w2 = w3; w3 = w4; w4 = v;
            if (yy >= 4) {
                float o = w0*tb[0] + w1*tb[1] + w2*tb[2] + w3*tb[3] + w4*tb[4];
                ov[(yy - 4) * 37] = o;
            }
        }
    }
    __syncthreads();

    {
        int ch = t & 31, yr = t >> 5;
        const float* vp = s_v + ch * 593 + yr * 37;
        float* ob = g_blur + ((long)(b * 224 + y0 + yr) * 224 + x0) * 256 + cb * 32 + ch;
        float a0 = vp[0], a1 = vp[1], a2 = vp[2], a3 = vp[3];
#pragma unroll
        for (int x = 0; x < 32; x++) {
            float a4 = vp[x + 4];
            float o = a0*tb[0] + a1*tb[1] + a2*tb[2] + a3*tb[3] + a4*tb[4];
            ob[x * 256] = o;
            a0 = a1; a1 = a2; a2 = a3; a3 = a4;
        }
    }
}

// ---------------- fused v9: staged weights + 4px float2 phase B ------------
// CTA: 2x8 output tile, 512 threads, 2 CTAs/SM.
// s_blur: 85 rows x 260 floats (parity-split 5x17 region):
//   even rix: row = riy*9 + rix/2 ; odd rix: row = 45 + riy*8 + rix/2
// s_w: double buffer, 2 x [9 k][256 c] fp32; staged per tap (overlaps compute)
// phase B: thread = (c2 = t&127 [float2 ch], pq = t>>7 [4 px: py=pq>>1,
//   xh=pq&1, px = 4*xh+i]). Per tap: 4 v-LDS.64 + 9 w-LDS.64 + 72 FMA.
//   1.44 B/FMA vs v8's 2.44 -> phase-B L1 bytes 884K -> 553K per CTA.
// warp = (pq, 64ch): butterfly -> 16 warp partials -> 4-warp combine.
// smem floats: s_blur 22100 | s_w 4608 | s_red 576 | s_logit 144 | s_attn 144
#define FUSED_SMEM ((22100 + 4608 + 576 + 144 + 144) * 4)

__device__ __forceinline__ void stage_tap(const float4* __restrict__ wp4,
                                          float* __restrict__ s_w,
                                          int buf, int tap, int t)
{
    // 576 float4 per tap (9 k x 64 c4)
    {
        int k = t >> 6, c4 = t & 63;
        *(float4*)(s_w + ((buf * 9 + k) * 64 + c4) * 4) =
            __ldg(&wp4[(k * 9 + tap) * 64 + c4]);
    }
    if (t < 64) {
        *(float4*)(s_w + ((buf * 9 + 8) * 64 + t) * 4) =
            __ldg(&wp4[(8 * 9 + tap) * 64 + t]);
    }
}

__global__ void __launch_bounds__(512, 2) fused_kernel(
    const void* __restrict__ maskp,
    const float* __restrict__ kbias,
    const float* __restrict__ lbias,
    float* __restrict__ out)
{
    extern __shared__ float sm[];
    float* s_blur  = sm;             // 22100
    float* s_w     = sm + 22100;     // 4608
    float* s_red   = sm + 26708;     // 576 = 16 warps x 36
    float* s_logit = sm + 27284;     // 144
    float* s_attn  = sm + 27428;     // 144

    int t = threadIdx.x;
    int b = blockIdx.z;
    int x0o = blockIdx.x * 8, y0o = blockIdx.y * 2;
    int rx0 = 2 * x0o - 1, ry0 = 2 * y0o - 1;

    const float4* wp4 = (const float4*)g_wp;   // kt stride 64 float4

    // ---- stage tap 0 weights + load 5x17 blurred region concurrently ----
    stage_tap(wp4, s_w, 0, 0, t);
    {
        int c4 = t & 63, rr = t >> 6;
        const float* gb = g_blur + (long)b * 224 * 224 * 256 + c4 * 4;
        for (int row = rr; row < 85; row += 8) {
            int riy, rix;
            if (row < 45) { riy = row / 9;  rix = 2 * (row - riy * 9); }
            else { int q = row - 45; riy = q >> 3; rix = 2 * (q & 7) + 1; }
            int iy = ry0 + riy, ix = rx0 + rix;
            float4 v = make_float4(0.f, 0.f, 0.f, 0.f);
            if (iy >= 0 && iy < 224 && ix >= 0 && ix < 224)
                v = __ldcs((const float4*)(gb + ((long)iy * 224 + ix) * 256));
            *(float4*)(s_blur + row * 260 + c4 * 4) = v;
        }
    }
    __syncthreads();

    // ---- phase B: logits. thread = (c2, pq), 4 pixels x 9 k x 2 ch ----
    {
        int c2 = t & 127, pq = t >> 7;
        int py = pq >> 1, xh = pq & 1;        // px_i = 4*xh + i
        const float2* sb2 = (const float2*)s_blur;   // row stride 130 float2
        const float2* sw2 = (const float2*)s_w;      // [buf*9+k]*128 + c2

        float acc[9][4];
#pragma unroll
        for (int k = 0; k < 9; k++)
#pragma unroll
            for (int i = 0; i < 4; i++) acc[k][i] = 0.f;

#pragma unroll
        for (int tap = 0; tap < 9; tap++) {
            // stage next tap into the other buffer (overlaps compute)
            if (tap < 8) stage_tap(wp4, s_w, (tap + 1) & 1, tap + 1, t);

            const int dy = tap / 3, dx = tap % 3;   // compile-time (unrolled)
            int riy = 2 * py + dy;
            int rbase = (dx & 1) ? (45 + riy * 8 + 4 * xh)
                                 : (riy * 9 + 4 * xh + (dx >> 1));
            float2 v0 = sb2[(rbase + 0) * 130 + c2];
            float2 v1 = sb2[(rbase + 1) * 130 + c2];
            float2 v2 = sb2[(rbase + 2) * 130 + c2];
            float2 v3 = sb2[(rbase + 3) * 130 + c2];
            int bufb = (tap & 1) * 9;
#pragma unroll
            for (int k = 0; k < 9; k++) {
                float2 w = sw2[(bufb + k) * 128 + c2];
                acc[k][0] = fmaf(v0.y, w.y, fmaf(v0.x, w.x, acc[k][0]));
                acc[k][1] = fmaf(v1.y, w.y, fmaf(v1.x, w.x, acc[k][1]));
                acc[k][2] = fmaf(v2.y, w.y, fmaf(v2.x, w.x, acc[k][2]));
                acc[k][3] = fmaf(v3.y, w.y, fmaf(v3.x, w.x, acc[k][3]));
            }
            __syncthreads();   // staging of tap+1 visible; buffer rotation safe
        }

        // butterfly over 32 lanes (64 channels per warp)
#pragma unroll
        for (int o = 16; o; o >>= 1)
#pragma unroll
            for (int k = 0; k < 9; k++) {
                acc[k][0] += __shfl_xor_sync(0xffffffffu, acc[k][0], o);
                acc[k][1] += __shfl_xor_sync(0xffffffffu, acc[k][1], o);
                acc[k][2] += __shfl_xor_sync(0xffffffffu, acc[k][2], o);
                acc[k][3] += __shfl_xor_sync(0xffffffffu, acc[k][3], o);
            }
        int w = t >> 5, lane = t & 31;
        if (lane == 0) {
#pragma unroll
            for (int k = 0; k < 9; k++)
#pragma unroll
                for (int i = 0; i < 4; i++)
                    s_red[w * 36 + k * 4 + i] = acc[k][i];
        }
    }
    __syncthreads();

    // ---- combine 4 warp-partials + kbias -> logits ----
    if (t < 144) {
        int p = t / 9, k = t - p * 9;
        int py = p >> 3, px = p & 7;
        int xh = px >> 2, i = px & 3;
        int pq = py * 2 + xh;
        float v = kbias[k];
#pragma unroll
        for (int j = 0; j < 4; j++)
            v += s_red[(pq * 4 + j) * 36 + k * 4 + i];
        s_logit[p * 9 + k] = v;
    }
    __syncthreads();

    // ---- softmax over 9 with keep_mask + logit_bias ----
    if (t < 16) {
        int p = t;
        int oy = y0o + (p >> 3), ox = x0o + (p & 7);
        int mm = g_mask_mode;
        float lg[9];
#pragma unroll
        for (int k = 0; k < 9; k++) {
            long midx = ((long)(b * 9 + k) * 112 + oy) * 112 + ox;
            bool keep;
            if (mm == 0)      keep = ((const unsigned char*)maskp)[midx] != 0;
            else if (mm == 1) keep = ((const int*)maskp)[midx] != 0;
            else              keep = ((const float*)maskp)[midx] != 0.f;
            lg[k] = (keep ? s_logit[p * 9 + k] : 0.f) + lbias[k];
        }
        float mx = lg[0];
#pragma unroll
        for (int k = 1; k < 9; k++) mx = fmaxf(mx, lg[k]);
        float e[9]; float ssum = 0.f;
#pragma unroll
        for (int k = 0; k < 9; k++) { e[k] = expf(lg[k] - mx); ssum += e[k]; }
        float invs = 1.0f / ssum;
#pragma unroll
        for (int k = 0; k < 9; k++) s_attn[p * 9 + k] = e[k] * invs;
    }
    __syncthreads();

    // ---- einsum: thread = (px = t&7, c4 = t>>3), float4 channels ----
    {
        int px = t & 7, c4 = t >> 3;   // c4 0..63
        const float4* sb4 = (const float4*)s_blur;
#pragma unroll
        for (int r = 0; r < 2; r++) {
            float4 o = make_float4(0.f, 0.f, 0.f, 0.f);
#pragma unroll
            for (int dy = 0; dy < 3; dy++) {
                int riy = 2 * r + dy;
#pragma unroll
                for (int dx = 0; dx < 3; dx++) {
                    int rix = 2 * px + dx;
                    int row = (rix & 1) ? (45 + riy * 8 + (rix >> 1))
                                        : (riy * 9 + (rix >> 1));
                    float4 v = sb4[row * 65 + c4];
                    float a = s_attn[(r * 8 + px) * 9 + dy * 3 + dx];
                    o.x = fmaf(v.x, a, o.x);
                    o.y = fmaf(v.y, a, o.y);
                    o.z = fmaf(v.z, a, o.z);
                    o.w = fmaf(v.w, a, o.w);
                }
            }
            long base = ((long)(b * 256 + c4 * 4) * 112 + y0o + r) * 112 + x0o + px;
            const long cs = (long)112 * 112;
            out[base]          = o.x;
            out[base + cs]     = o.y;
            out[base + 2 * cs] = o.z;
            out[base + 3 * cs] = o.w;
        }
    }
}

// ---------------- launch ----------------
extern "C" void kernel_launch(void* const* d_in, const int* in_sizes, int n_in,
                              void* d_out, int out_size) {
    const float* hr  = (const float*)d_in[0];
    const float* ak  = (const float*)d_in[1];
    const float* kb  = (const float*)d_in[2];
    const float* lb  = (const float*)d_in[3];
    const void*  msk = d_in[4];
    float* out = (float*)d_out;
    (void)in_sizes; (void)n_in; (void)out_size;

    cudaFuncSetAttribute(blur_kernel,  cudaFuncAttributeMaxDynamicSharedMemorySize, BLUR_SMEM);
    cudaFuncSetAttribute(fused_kernel, cudaFuncAttributeMaxDynamicSharedMemorySize, FUSED_SMEM);

    detect_mask_kernel<<<1, 32>>>((const unsigned*)msk);
    repack_kernel<<<81, 256>>>(ak);
    blur_kernel<<<dim3(98, 8, 4), 512, BLUR_SMEM>>>(hr);
    fused_kernel<<<dim3(14, 56, 4), 512, FUSED_SMEM>>>(msk, kb, lb, out);
}

// round 13
// speedup vs baseline: 1.4702x; 1.0417x over previous
#include <cuda_runtime.h>
#include <math.h>

// ---------------- device scratch ----------------
__device__ float g_blur[4 * 224 * 224 * 256];   // blurred feats, layout [b][y][x][c]
__device__ float g_wp[81 * 256];                // weights repacked [k*9+tap][c]
__device__ int   g_mask_mode;                   // 0=uint8, 1=int32, 2=float32

// ---------------- mask dtype detection ----------------
__global__ void detect_mask_kernel(const unsigned* __restrict__ m) {
    int lane = threadIdx.x;  // 32 threads
    int fcount = 0, zocount = 0;
#pragma unroll
    for (int i = 0; i < 8; i++) {
        unsigned w = m[lane * 8 + i];
        if (w == 0x3f800000u) fcount++;
        if (w <= 1u) zocount++;
    }
#pragma unroll
    for (int o = 16; o; o >>= 1) {
        fcount  += __shfl_xor_sync(0xffffffffu, fcount, o);
        zocount += __shfl_xor_sync(0xffffffffu, zocount, o);
    }
    if (lane == 0) g_mask_mode = (fcount > 0) ? 2 : ((zocount == 256) ? 1 : 0);
}

// ---------------- weight repack: (9,256,3,3) -> [k*9+tap][c] ----------------
__global__ void repack_kernel(const float* __restrict__ ak) {
    int idx = blockIdx.x * 256 + threadIdx.x;  // 81 blocks * 256 = 20736
    int c  = idx & 255;
    int kt = idx >> 8;           // k*9 + tap, 0..80
    int k = kt / 9, tap = kt - k * 9;
    g_wp[idx] = ak[(k * 256 + c) * 9 + tap];
}

// ---------------- separable 5x5 gaussian blur (proven R3 config) -----------
#define BLUR_SMEM (32 * 593 * 4)

__global__ void __launch_bounds__(512, 2) blur_kernel(const float* __restrict__ hr) {
    extern __shared__ float s_v[];

    const float C = -1.4142135623730951f;
    float tb[5]; float s = 0.f;
#pragma unroll
    for (int j = 0; j < 5; j++) { float d = (float)(j - 2); tb[j] = expf(d * d * C); s += tb[j]; }
#pragma unroll
    for (int j = 0; j < 5; j++) tb[j] = tb[j] / s;

    int b = blockIdx.z, cb = blockIdx.y;
    int tx = blockIdx.x % 7, ty = blockIdx.x / 7;
    int x0 = tx * 32, y0 = ty * 16;
    int t = threadIdx.x;

    for (int j = t; j < 1152; j += 512) {
        int ch = j / 36, lx = j - ch * 36;
        int ix = x0 - 2 + lx;
        bool vx = (ix >= 0 && ix < 224);
        const float* base = hr + ((long)(b * 256 + cb * 32 + ch) * 224) * 224 + ix;
        float w0 = 0.f, w1 = 0.f, w2 = 0.f, w3 = 0.f, w4 = 0.f;
        float* ov = s_v + ch * 593 + lx;
#pragma unroll
        for (int yy = 0; yy < 20; yy++) {
            int iy = y0 - 2 + yy;
            float v = (vx && iy >= 0 && iy < 224) ? base[iy * 224] : 0.f;
            w0 = w1; w1 = w2; w2 = w3; w3 = w4; w4 = v;
            if (yy >= 4) {
                float o = w0*tb[0] + w1*tb[1] + w2*tb[2] + w3*tb[3] + w4*tb[4];
                ov[(yy - 4) * 37] = o;
            }
        }
    }
    __syncthreads();

    {
        int ch = t & 31, yr = t >> 5;
        const float* vp = s_v + ch * 593 + yr * 37;
        float* ob = g_blur + ((long)(b * 224 + y0 + yr) * 224 + x0) * 256 + cb * 32 + ch;
        float a0 = vp[0], a1 = vp[1], a2 = vp[2], a3 = vp[3];
#pragma unroll
        for (int x = 0; x < 32; x++) {
            float a4 = vp[x + 4];
            float o = a0*tb[0] + a1*tb[1] + a2*tb[2] + a3*tb[3] + a4*tb[4];
            ob[x * 256] = o;
            a0 = a1; a1 = a2; a2 = a3; a3 = a4;
        }
    }
}

// ---------------- fused v10: persistent + cp.async double buffer -----------
// Grid = 148 CTAs (1/SM), 512 threads, each CTA processes tiles
// cta, cta+148, ... (3136 total). Region of tile n+1 prefetched via
// cp.async.cg into the other buffer while tile n computes.
// Per-tile compute identical to v9 (tap-staged weights, float2 phase B,
// float4 einsum). Full fp32.
// smem floats: s_blur 2x22100 | s_w 4608 | s_red 576 | s_logit 144 | s_attn 144
#define GRID_F 148
#define TILES_TOTAL 3136
#define FUSED_SMEM ((44200 + 4608 + 576 + 144 + 144) * 4)

__device__ __forceinline__ void stage_tap(const float4* __restrict__ wp4,
                                          float* __restrict__ s_w,
                                          int buf, int tap, int t)
{
    {
        int k = t >> 6, c4 = t & 63;
        *(float4*)(s_w + ((buf * 9 + k) * 64 + c4) * 4) =
            __ldg(&wp4[(k * 9 + tap) * 64 + c4]);
    }
    if (t < 64) {
        *(float4*)(s_w + ((buf * 9 + 8) * 64 + t) * 4) =
            __ldg(&wp4[(8 * 9 + tap) * 64 + t]);
    }
}

// issue cp.async for tile's 85-row region into s_dst (zero-fill OOB)
__device__ __forceinline__ void prefetch_region(int tile, float* s_dst, int t) {
    int b = tile / 784;
    int rem = tile - b * 784;
    int ty = rem / 14, tx = rem - ty * 14;
    int rx0 = 2 * (tx * 8) - 1, ry0 = 2 * (ty * 2) - 1;
    int c4 = t & 63, rr = t >> 6;
    const float* gb = g_blur + (long)b * 224 * 224 * 256 + c4 * 4;
#pragma unroll
    for (int row = rr; row < 85; row += 8) {
        int riy, rix;
        if (row < 45) { riy = row / 9;  rix = 2 * (row - riy * 9); }
        else { int q = row - 45; riy = q >> 3; rix = 2 * (q & 7) + 1; }
        int iy = ry0 + riy, ix = rx0 + rix;
        bool ok = (iy >= 0 && iy < 224 && ix >= 0 && ix < 224);
        const float* src = ok ? (gb + ((long)iy * 224 + ix) * 256) : gb;
        unsigned dst = (unsigned)__cvta_generic_to_shared(s_dst + row * 260 + c4 * 4);
        int sz = ok ? 16 : 0;
        asm volatile("cp.async.cg.shared.global [%0], [%1], 16, %2;\n"
                     :: "r"(dst), "l"(src), "r"(sz));
    }
}

__global__ void __launch_bounds__(512) fused_kernel(
    const void* __restrict__ maskp,
    const float* __restrict__ kbias,
    const float* __restrict__ lbias,
    float* __restrict__ out)
{
    extern __shared__ float sm[];
    float* s_blurA = sm;             // 2 x 22100
    float* s_w     = sm + 44200;     // 4608
    float* s_red   = sm + 48808;     // 576
    float* s_logit = sm + 49384;     // 144
    float* s_attn  = sm + 49528;     // 144

    int t = threadIdx.x;
    const float4* wp4 = (const float4*)g_wp;
    int mm = g_mask_mode;

    // hoisted per-thread constants for combine phase (t < 144)
    float kb_r = 0.f, lb_r = 0.f;
    if (t < 144) { int k = t % 9; kb_r = kbias[k]; lb_r = lbias[k]; }

    int n = blockIdx.x;
    int buf = 0;

    // prefetch first tile
    prefetch_region(n, s_blurA, t);
    asm volatile("cp.async.commit_group;\n");

    while (n < TILES_TOTAL) {
        int n2 = n + GRID_F;
        if (n2 < TILES_TOTAL)
            prefetch_region(n2, s_blurA + (buf ^ 1) * 22100, t);
        asm volatile("cp.async.commit_group;\n");

        // stage tap-0 weights while waiting on region
        stage_tap(wp4, s_w, 0, 0, t);
        asm volatile("cp.async.wait_group 1;\n");
        __syncthreads();

        float* s_blur = s_blurA + buf * 22100;
        int b = n / 784;
        int rem = n - b * 784;
        int tyi = rem / 14, txi = rem - tyi * 14;
        int x0o = txi * 8, y0o = tyi * 2;

        // ---- phase B: logits. thread = (c2, pq), 4 pixels x 9 k ----
        {
            int c2 = t & 127, pq = t >> 7;
            int py = pq >> 1, xh = pq & 1;
            const float2* sb2 = (const float2*)s_blur;   // row stride 130
            const float2* sw2 = (const float2*)s_w;      // [buf*9+k]*128 + c2

            float acc[9][4];
#pragma unroll
            for (int k = 0; k < 9; k++)
#pragma unroll
                for (int i = 0; i < 4; i++) acc[k][i] = 0.f;

#pragma unroll
            for (int tap = 0; tap < 9; tap++) {
                if (tap < 8) stage_tap(wp4, s_w, (tap + 1) & 1, tap + 1, t);

                const int dy = tap / 3, dx = tap % 3;
                int riy = 2 * py + dy;
                int rbase = (dx & 1) ? (45 + riy * 8 + 4 * xh)
                                     : (riy * 9 + 4 * xh + (dx >> 1));
                float2 v0 = sb2[(rbase + 0) * 130 + c2];
                float2 v1 = sb2[(rbase + 1) * 130 + c2];
                float2 v2 = sb2[(rbase + 2) * 130 + c2];
                float2 v3 = sb2[(rbase + 3) * 130 + c2];
                int bufb = (tap & 1) * 9;
#pragma unroll
                for (int k = 0; k < 9; k++) {
                    float2 w = sw2[(bufb + k) * 128 + c2];
                    acc[k][0] = fmaf(v0.y, w.y, fmaf(v0.x, w.x, acc[k][0]));
                    acc[k][1] = fmaf(v1.y, w.y, fmaf(v1.x, w.x, acc[k][1]));
                    acc[k][2] = fmaf(v2.y, w.y, fmaf(v2.x, w.x, acc[k][2]));
                    acc[k][3] = fmaf(v3.y, w.y, fmaf(v3.x, w.x, acc[k][3]));
                }
                __syncthreads();
            }

#pragma unroll
            for (int o = 16; o; o >>= 1)
#pragma unroll
                for (int k = 0; k < 9; k++) {
                    acc[k][0] += __shfl_xor_sync(0xffffffffu, acc[k][0], o);
                    acc[k][1] += __shfl_xor_sync(0xffffffffu, acc[k][1], o);
                    acc[k][2] += __shfl_xor_sync(0xffffffffu, acc[k][2], o);
                    acc[k][3] += __shfl_xor_sync(0xffffffffu, acc[k][3], o);
                }
            int w = t >> 5, lane = t & 31;
            if (lane == 0) {
#pragma unroll
                for (int k = 0; k < 9; k++)
#pragma unroll
                    for (int i = 0; i < 4; i++)
                        s_red[w * 36 + k * 4 + i] = acc[k][i];
            }
        }
        __syncthreads();

        // ---- combine + kbias + mask + lbias -> masked logits ----
        if (t < 144) {
            int p = t / 9, k = t - p * 9;
            int py = p >> 3, px = p & 7;
            int xh = px >> 2, i = px & 3;
            int pq = py * 2 + xh;
            float v = kb_r;
#pragma unroll
            for (int j = 0; j < 4; j++)
                v += s_red[(pq * 4 + j) * 36 + k * 4 + i];
            int oy = y0o + py, ox = x0o + px;
            long midx = ((long)(b * 9 + k) * 112 + oy) * 112 + ox;
            bool keep;
            if (mm == 0)      keep = ((const unsigned char*)maskp)[midx] != 0;
            else if (mm == 1) keep = ((const int*)maskp)[midx] != 0;
            else              keep = ((const float*)maskp)[midx] != 0.f;
            s_logit[p * 9 + k] = (keep ? v : 0.f) + lb_r;
        }
        __syncthreads();

        // ---- softmax over 9 ----
        if (t < 16) {
            int p = t;
            float lg[9];
#pragma unroll
            for (int k = 0; k < 9; k++) lg[k] = s_logit[p * 9 + k];
            float mx = lg[0];
#pragma unroll
            for (int k = 1; k < 9; k++) mx = fmaxf(mx, lg[k]);
            float e[9]; float ssum = 0.f;
#pragma unroll
            for (int k = 0; k < 9; k++) { e[k] = expf(lg[k] - mx); ssum += e[k]; }
            float invs = 1.0f / ssum;
#pragma unroll
            for (int k = 0; k < 9; k++) s_attn[p * 9 + k] = e[k] * invs;
        }
        __syncthreads();

        // ---- einsum: thread = (px = t&7, c4 = t>>3), float4 channels ----
        {
            int px = t & 7, c4 = t >> 3;
            const float4* sb4 = (const float4*)s_blur;
#pragma unroll
            for (int r = 0; r < 2; r++) {
                float4 o = make_float4(0.f, 0.f, 0.f, 0.f);
#pragma unroll
                for (int dy = 0; dy < 3; dy++) {
                    int riy = 2 * r + dy;
#pragma unroll
                    for (int dx = 0; dx < 3; dx++) {
                        int rix = 2 * px + dx;
                        int row = (rix & 1) ? (45 + riy * 8 + (rix >> 1))
                                            : (riy * 9 + (rix >> 1));
                        float4 v = sb4[row * 65 + c4];
                        float a = s_attn[(r * 8 + px) * 9 + dy * 3 + dx];
                        o.x = fmaf(v.x, a, o.x);
                        o.y = fmaf(v.y, a, o.y);
                        o.z = fmaf(v.z, a, o.z);
                        o.w = fmaf(v.w, a, o.w);
                    }
                }
                long base = ((long)(b * 256 + c4 * 4) * 112 + y0o + r) * 112 + x0o + px;
                const long cs = (long)112 * 112;
                out[base]          = o.x;
                out[base + cs]     = o.y;
                out[base + 2 * cs] = o.z;
                out[base + 3 * cs] = o.w;
            }
        }
        __syncthreads();   // protect region buffer & s_attn before next tile

        buf ^= 1;
        n = n2;
    }
}

// ---------------- launch ----------------
extern "C" void kernel_launch(void* const* d_in, const int* in_sizes, int n_in,
                              void* d_out, int out_size) {
    const float* hr  = (const float*)d_in[0];
    const float* ak  = (const float*)d_in[1];
    const float* kb  = (const float*)d_in[2];
    const float* lb  = (const float*)d_in[3];
    const void*  msk = d_in[4];
    float* out = (float*)d_out;
    (void)in_sizes; (void)n_in; (void)out_size;

    cudaFuncSetAttribute(blur_kernel,  cudaFuncAttributeMaxDynamicSharedMemorySize, BLUR_SMEM);
    cudaFuncSetAttribute(fused_kernel, cudaFuncAttributeMaxDynamicSharedMemorySize, FUSED_SMEM);

    detect_mask_kernel<<<1, 32>>>((const unsigned*)msk);
    repack_kernel<<<81, 256>>>(ak);
    blur_kernel<<<dim3(98, 8, 4), 512, BLUR_SMEM>>>(hr);
    fused_kernel<<<GRID_F, 512, FUSED_SMEM>>>(msk, kb, lb, out);
}